// round 11
// baseline (speedup 1.0000x reference)
#include <cuda_runtime.h>
#include <cuda_bf16.h>
#include <cstdint>

#define S       512
#define TMAXX   2048
#define OBS     1024
#define NT      512
#define NCTAS   128

#define LOG64F   4.158883083359672f
#define LOG16384 9.704060527839234

// ---- smem layout (bytes) ----
// B buffers: [2 buf][2 slice][528]  slice = [b 0..1][256 p] e5m2 (512B) + zp float2 (8B) + pad
#define B_OFF   0
#define SLICE   528
#define BUFSTR  1056
#define ZR_OFF  2112      // [16 warps] float2 partial z
#define Z0_OFF  2240      // init z (2 f32)
#define TS_OFF  2248      // Ts[2] int
#define BAR_OFF 2256      // full0, full1 @+0,+8 ; empty0, empty1 @+16,+24
#define SMEM_BYTES 2304

// ---------------- device tables ----------------
__device__ float g_expA[S * S];      // [n][p]
__device__ float g_expEt[OBS * S];   // [o][n]
__device__ float g_expPi[S];

// ---------------- helpers ----------------
__device__ __forceinline__ float warp_max(float v) {
    #pragma unroll
    for (int o = 16; o; o >>= 1) v = fmaxf(v, __shfl_xor_sync(0xffffffffu, v, o));
    return v;
}
__device__ __forceinline__ float warp_sum(float v) {
    #pragma unroll
    for (int o = 16; o; o >>= 1) v += __shfl_xor_sync(0xffffffffu, v, o);
    return v;
}
__device__ __forceinline__ uint32_t mapa_u32(uint32_t addr, int rank) {
    uint32_t r;
    asm("mapa.shared::cluster.u32 %0, %1, %2;" : "=r"(r) : "r"(addr), "r"(rank));
    return r;
}
__device__ __forceinline__ void mbar_init(uint32_t addr, uint32_t cnt) {
    asm volatile("mbarrier.init.shared.b64 [%0], %1;" :: "r"(addr), "r"(cnt) : "memory");
}
__device__ __forceinline__ void mbar_arrive_expect(uint32_t addr, uint32_t tx) {
    asm volatile("mbarrier.arrive.expect_tx.shared.b64 _, [%0], %1;" :: "r"(addr), "r"(tx) : "memory");
}
__device__ __forceinline__ void mbar_arrive_local(uint32_t addr) {
    asm volatile("mbarrier.arrive.shared.b64 _, [%0];" :: "r"(addr) : "memory");
}
__device__ __forceinline__ void mbar_arrive_remote(uint32_t remAddr) {
    asm volatile("mbarrier.arrive.shared::cluster.b64 _, [%0];" :: "r"(remAddr) : "memory");
}
__device__ __forceinline__ void mbar_wait(uint32_t addr, uint32_t parity) {
    uint32_t done;
    asm volatile(
        "{\n\t.reg .pred p;\n\t"
        "mbarrier.try_wait.parity.acquire.cta.shared::cta.b64 p, [%1], %2;\n\t"
        "selp.b32 %0, 1, 0, p;\n\t}"
        : "=r"(done) : "r"(addr), "r"(parity) : "memory");
    if (!done) {
        asm volatile(
            "{\n\t.reg .pred P1;\n\t"
            "WL_%=:\n\t"
            "mbarrier.try_wait.parity.acquire.cta.shared::cta.b64 P1, [%0], %1, 0x989680;\n\t"
            "@P1 bra.uni WD_%=;\n\t"
            "bra.uni WL_%=;\n\t"
            "WD_%=:\n\t}"
            :: "r"(addr), "r"(parity) : "memory");
    }
}
__device__ __forceinline__ void bulk_s2s(uint32_t dst_cluster, uint32_t src_cta,
                                         uint32_t bytes, uint32_t mbar_cluster) {
    asm volatile(
        "cp.async.bulk.shared::cluster.shared::cta.mbarrier::complete_tx::bytes [%0], [%1], %2, [%3];"
        :: "r"(dst_cluster), "r"(src_cta), "r"(bytes), "r"(mbar_cluster) : "memory");
}
__device__ __forceinline__ void fence_proxy_async_() {
    asm volatile("fence.proxy.async.shared::cta;" ::: "memory");
}
__device__ __forceinline__ void cluster_sync_() {
    asm volatile("barrier.cluster.arrive.aligned;\n" ::: "memory");
    asm volatile("barrier.cluster.wait.aligned;\n" ::: "memory");
}
__device__ __forceinline__ uint32_t lds_u32(uint32_t addr) {
    uint32_t v;
    asm volatile("ld.shared.u32 %0, [%1];" : "=r"(v) : "r"(addr));
    return v;
}
__device__ __forceinline__ void sts_u8(uint32_t addr, uint32_t v) {
    asm volatile("st.shared.u8 [%0], %1;" :: "r"(addr), "r"(v) : "memory");
}
// d = {e4m3(hi) in bits 15:8, e4m3(lo) in bits 7:0}
__device__ __forceinline__ uint32_t cvt_e4m3x2(float hi, float lo) {
    uint16_t d;
    asm("cvt.rn.satfinite.e4m3x2.f32 %0, %1, %2;" : "=h"(d) : "f"(hi), "f"(lo));
    return (uint32_t)d;
}
// d = {e5m2(hi) in bits 15:8, e5m2(lo) in bits 7:0}
__device__ __forceinline__ uint32_t cvt_e5m2x2(float hi, float lo) {
    uint16_t d;
    asm("cvt.rn.satfinite.e5m2x2.f32 %0, %1, %2;" : "=h"(d) : "f"(hi), "f"(lo));
    return (uint32_t)d;
}
__device__ __forceinline__ uint32_t pack4_e4m3(float f0, float f1, float f2, float f3) {
    uint32_t lo = cvt_e4m3x2(f1, f0);          // byte0=f0, byte1=f1
    uint32_t hi = cvt_e4m3x2(f3, f2);          // byte2=f2, byte3=f3
    return lo | (hi << 16);
}
// A is e4m3, B (v) is e5m2
__device__ __forceinline__ void qmma(float& c0, float& c1, float& c2, float& c3,
                                     uint32_t a0, uint32_t a1, uint32_t a2, uint32_t a3,
                                     uint32_t b0, uint32_t b1) {
    asm volatile(
        "mma.sync.aligned.m16n8k32.row.col.f32.e4m3.e5m2.f32 "
        "{%0,%1,%2,%3}, {%4,%5,%6,%7}, {%8,%9}, {%0,%1,%2,%3};"
        : "+f"(c0), "+f"(c1), "+f"(c2), "+f"(c3)
        : "r"(a0), "r"(a1), "r"(a2), "r"(a3), "r"(b0), "r"(b1));
}

// ---------------- prep kernels (unchanged math) ----------------
__global__ void prep_pi(const float* __restrict__ pi) {
    __shared__ float red[16];
    int tid = threadIdx.x;
    float v = pi[tid];
    float m = warp_max(v);
    if ((tid & 31) == 0) red[tid >> 5] = m;
    __syncthreads();
    float bm = red[0];
    #pragma unroll
    for (int i = 1; i < 16; i++) bm = fmaxf(bm, red[i]);
    __syncthreads();
    float e = expf(v - bm);
    float s = warp_sum(e);
    if ((tid & 31) == 0) red[tid >> 5] = s;
    __syncthreads();
    float bs = 0.f;
    #pragma unroll
    for (int i = 0; i < 16; i++) bs += red[i];
    g_expPi[tid] = e / bs;
}

__global__ void prep_A(const float* __restrict__ trans) {
    __shared__ float red[4];
    int p = blockIdx.x, tid = threadIdx.x;
    int lane = tid & 31, w = tid >> 5;
    float v[4];
    #pragma unroll
    for (int k = 0; k < 4; k++) v[k] = trans[(tid + 128 * k) * S + p];
    float m = fmaxf(fmaxf(v[0], v[1]), fmaxf(v[2], v[3]));
    m = warp_max(m);
    if (lane == 0) red[w] = m;
    __syncthreads();
    float bm = fmaxf(fmaxf(red[0], red[1]), fmaxf(red[2], red[3]));
    __syncthreads();
    float e[4], s = 0.f;
    #pragma unroll
    for (int k = 0; k < 4; k++) { e[k] = expf(v[k] - bm); s += e[k]; }
    s = warp_sum(s);
    if (lane == 0) red[w] = s;
    __syncthreads();
    float bs = red[0] + red[1] + red[2] + red[3];
    float inv = 1.0f / bs;
    #pragma unroll
    for (int k = 0; k < 4; k++) g_expA[(tid + 128 * k) * S + p] = e[k] * inv;
}

__global__ void prep_E(const float* __restrict__ emis) {
    __shared__ float red[8];
    int n = blockIdx.x, tid = threadIdx.x;
    int lane = tid & 31, w = tid >> 5;
    float v[4];
    #pragma unroll
    for (int k = 0; k < 4; k++) v[k] = emis[n * OBS + tid + 256 * k];
    float m = fmaxf(fmaxf(v[0], v[1]), fmaxf(v[2], v[3]));
    m = warp_max(m);
    if (lane == 0) red[w] = m;
    __syncthreads();
    float bm = red[0];
    #pragma unroll
    for (int i = 1; i < 8; i++) bm = fmaxf(bm, red[i]);
    __syncthreads();
    float e[4], s = 0.f;
    #pragma unroll
    for (int k = 0; k < 4; k++) { e[k] = expf(v[k] - bm); s += e[k]; }
    s = warp_sum(s);
    if (lane == 0) red[w] = s;
    __syncthreads();
    float bs = 0.f;
    #pragma unroll
    for (int i = 0; i < 8; i++) bs += red[i];
    float inv = 1.0f / bs;
    #pragma unroll
    for (int k = 0; k < 4; k++) g_expEt[(tid + 256 * k) * S + n] = e[k] * inv;
}

// ---------------- main: e4m3xe5m2 QMMA scaled forward, CL=2 ----------------
__global__ void __cluster_dims__(2, 1, 1) __launch_bounds__(NT, 1)
hmm_main(const int* __restrict__ x, const int* __restrict__ T, float* __restrict__ out) {
    extern __shared__ char smc[];
    int* Ts_sh = (int*)(smc + TS_OFF);

    const int tid = threadIdx.x, wid = tid >> 5, lane = tid & 31;
    const int g = lane >> 2, tg = lane & 3;
    const int rank = blockIdx.x & 1, peer = rank ^ 1;
    const int b0g = (blockIdx.x >> 1) * 2;
    const int nbase = rank * 256;

    const uint32_t smb  = (uint32_t)__cvta_generic_to_shared(smc);
    const uint32_t barF = smb + BAR_OFF;          // full[buf] = barF + buf*8
    const uint32_t barE = smb + BAR_OFF + 16;     // empty[buf]

    // ---- barriers ----
    if (tid == 0) {
        mbar_init(barF + 0, 2);  mbar_init(barF + 8, 2);
        mbar_init(barE + 0, 1);  mbar_init(barE + 8, 1);
        mbar_arrive_expect(barF + 0, SLICE);      // arm both (arrival 1 of 2)
        mbar_arrive_expect(barF + 8, SLICE);
    }
    if (tid < 2) Ts_sh[tid] = T[b0g + tid];

    // ---- v0: all 512 p, both batches, local ----
    const int x0a = __ldg(&x[b0g * TMAXX]);
    const int x0b = __ldg(&x[(b0g + 1) * TMAXX]);
    float va = __ldg(&g_expEt[x0a * S + tid]) * __ldg(&g_expPi[tid]);
    float vb = __ldg(&g_expEt[x0b * S + tid]) * __ldg(&g_expPi[tid]);
    {
        float sa = warp_sum(va), sb = warp_sum(vb);
        if (lane == 0) *(float2*)(smc + ZR_OFF + wid * 8) = make_float2(sa, sb);
    }
    __syncthreads();
    if (tid == 0) {
        float h0a = 0.f, h0b = 0.f, h1a = 0.f, h1b = 0.f;
        #pragma unroll
        for (int w = 0; w < 8; w++) {
            float2 z = *(float2*)(smc + ZR_OFF + w * 8);
            h0a += z.x; h0b += z.y;
        }
        #pragma unroll
        for (int w = 8; w < 16; w++) {
            float2 z = *(float2*)(smc + ZR_OFF + w * 8);
            h1a += z.x; h1b += z.y;
        }
        float za = h0a + h1a, zb = h0b + h1b;
        *(float2*)(smc + B_OFF + 0 * SLICE + 512) = make_float2(64.f * h0a / za, 64.f * h0b / zb);
        *(float2*)(smc + B_OFF + 1 * SLICE + 512) = make_float2(64.f * h1a / za, 64.f * h1b / zb);
        *(float2*)(smc + Z0_OFF) = make_float2(za, zb);
    }
    __syncthreads();
    {
        float2 z0 = *(float2*)(smc + Z0_OFF);
        float sca = 64.f / z0.x, scb = 64.f / z0.y;
        int s = tid >> 8, pl = tid & 255;
        uint32_t t01 = cvt_e5m2x2(vb * scb, va * sca);    // lo=va', hi=vb'
        uint32_t sl = smb + B_OFF + s * SLICE;
        sts_u8(sl + pl, t01);                              // row b=0
        sts_u8(sl + 256 + pl, t01 >> 8);                   // row b=1
    }

    // ---- A fragments in registers (x256, e4m3): warp wid -> rows nbase+16*wid..+15, full k ----
    uint32_t Ar[16][4];
    {
        const float* A0 = &g_expA[(nbase + wid * 16 + g) * S];
        const float* A1 = A0 + 8 * S;
        #pragma unroll
        for (int c = 0; c < 16; c++) {
            int k0 = 32 * c + 4 * tg;
            Ar[c][0] = pack4_e4m3(256.f * __ldg(A0 + k0),      256.f * __ldg(A0 + k0 + 1),
                                  256.f * __ldg(A0 + k0 + 2),  256.f * __ldg(A0 + k0 + 3));
            Ar[c][1] = pack4_e4m3(256.f * __ldg(A1 + k0),      256.f * __ldg(A1 + k0 + 1),
                                  256.f * __ldg(A1 + k0 + 2),  256.f * __ldg(A1 + k0 + 3));
            Ar[c][2] = pack4_e4m3(256.f * __ldg(A0 + k0 + 16), 256.f * __ldg(A0 + k0 + 17),
                                  256.f * __ldg(A0 + k0 + 18), 256.f * __ldg(A0 + k0 + 19));
            Ar[c][3] = pack4_e4m3(256.f * __ldg(A1 + k0 + 16), 256.f * __ldg(A1 + k0 + 17),
                                  256.f * __ldg(A1 + k0 + 18), 256.f * __ldg(A1 + k0 + 19));
        }
    }
    __syncthreads();
    cluster_sync_();

    const int maxT = max(Ts_sh[0], Ts_sh[1]);
    double off0 = 0.0, off1 = 0.0;
    if (rank == 0 && tid == 0) {
        float2 z0 = *(float2*)(smc + Z0_OFF);
        off0 = (double)logf(z0.x) - (double)LOG64F;
        off1 = (double)logf(z0.y) - (double)LOG64F;
    }

    const int n0 = nbase + wid * 16 + g;           // epilogue rows n0, n0+8 (tg==0)
    const int nl0 = wid * 16 + g;
    int cur = 0;
    uint32_t pf0 = 0, pf1 = 0, pe0 = 0, pe1 = 0;

    for (int t = 1; ; ++t) {
        const int nxt = cur ^ 1;

        // ---- prefetch E (tg==0 lanes) ----
        float E00 = 0.f, E01 = 0.f, E10 = 0.f, E11 = 0.f;
        if (tg == 0) {
            int tt = t < TMAXX ? t : TMAXX - 1;
            int xa = __ldg(&x[b0g * TMAXX + tt]);
            int xc = __ldg(&x[(b0g + 1) * TMAXX + tt]);
            E00 = __ldg(&g_expEt[xa * S + n0]);
            E01 = __ldg(&g_expEt[xa * S + n0 + 8]);
            E10 = __ldg(&g_expEt[xc * S + n0]);
            E11 = __ldg(&g_expEt[xc * S + n0 + 8]);
        }

        // ---- wait remote+local slice readiness ----
        if (t > 1) {
            mbar_wait(barF + cur * 8, cur ? pf1 : pf0);
            if (cur) pf1 ^= 1; else pf0 ^= 1;
        }

        // ---- per-warp z, rz (lane 0), out/off (rank0 warp0 lane0) ----
        float rz0, rz1;
        if (lane == 0) {
            float2 zpa = *(float2*)(smc + B_OFF + cur * BUFSTR + 512);
            float2 zpb = *(float2*)(smc + B_OFF + cur * BUFSTR + SLICE + 512);
            float z0 = zpa.x + zpb.x, z1 = zpa.y + zpb.y;
            rz0 = __fdividef(64.f, z0);
            rz1 = __fdividef(64.f, z1);
            if (rank == 0 && wid == 0) {
                float l0 = logf(z0), l1 = logf(z1);
                if (Ts_sh[0] == t) out[b0g]     = (float)(off0 + (double)l0);
                if (Ts_sh[1] == t) out[b0g + 1] = (float)(off1 + (double)l1);
                off0 += (double)l0 - LOG16384;
                off1 += (double)l1 - LOG16384;
            }
        }
        if (t == maxT) break;
        rz0 = __shfl_sync(0xffffffffu, rz0, 0);
        rz1 = __shfl_sync(0xffffffffu, rz1, 0);

        // ---- QMMA: D[16 rows, cols b] = A rows x full k=512 ----
        float c0 = 0.f, c1 = 0.f, c2 = 0.f, c3 = 0.f;
        {
            const uint32_t vb0 = smb + B_OFF + cur * BUFSTR + g * 256 + 4 * tg;
            #pragma unroll
            for (int c = 0; c < 16; c++) {
                uint32_t addr = vb0 + (uint32_t)((c >> 3) * SLICE + (c & 7) * 32);
                uint32_t b0r = (g < 2) ? lds_u32(addr) : 0u;
                uint32_t b1r = (g < 2) ? lds_u32(addr + 16) : 0u;
                qmma(c0, c1, c2, c3, Ar[c][0], Ar[c][1], Ar[c][2], Ar[c][3], b0r, b1r);
            }
        }

        // ---- epilogue (tg==0): scale, cvt e5m2, store local slice; z partials ----
        float sb0 = 0.f, sb1 = 0.f;
        {
            const uint32_t slb = smb + B_OFF + nxt * BUFSTR + rank * SLICE;
            if (tg == 0) {
                float w00 = c0 * E00 * rz0;    // (n0,   b0)
                float w01 = c1 * E10 * rz1;    // (n0,   b1)
                float w10 = c2 * E01 * rz0;    // (n0+8, b0)
                float w11 = c3 * E11 * rz1;    // (n0+8, b1)
                uint32_t t0 = cvt_e5m2x2(w10, w00);   // lo=(n0,b0) hi=(n0+8,b0)
                uint32_t t1 = cvt_e5m2x2(w11, w01);
                sts_u8(slb + nl0, t0);
                sts_u8(slb + nl0 + 8, t0 >> 8);
                sts_u8(slb + 256 + nl0, t1);
                sts_u8(slb + 256 + nl0 + 8, t1 >> 8);
                sb0 = w00 + w10;
                sb1 = w01 + w11;
            }
            #pragma unroll
            for (int o = 16; o >= 4; o >>= 1) {
                sb0 += __shfl_xor_sync(0xffffffffu, sb0, o);
                sb1 += __shfl_xor_sync(0xffffffffu, sb1, o);
            }
            if (lane == 0) *(float2*)(smc + ZR_OFF + wid * 8) = make_float2(sb0, sb1);
        }

        // ---- barrier: only warp0 blocks ----
        if (wid != 0) {
            asm volatile("bar.arrive 1, %0;" :: "r"(NT) : "memory");
        } else {
            asm volatile("bar.sync 1, %0;" :: "r"(NT) : "memory");
            // zp totals over 16 warps
            float2 zr = (lane < 16) ? *(float2*)(smc + ZR_OFF + lane * 8) : make_float2(0.f, 0.f);
            #pragma unroll
            for (int o = 8; o >= 1; o >>= 1) {
                zr.x += __shfl_xor_sync(0xffffffffu, zr.x, o);
                zr.y += __shfl_xor_sync(0xffffffffu, zr.y, o);
            }
            if (lane == 0) {
                uint32_t slb = smb + B_OFF + nxt * BUFSTR + rank * SLICE;
                *(float2*)(smc + (slb - smb) + 512) = zr;
                if (t > 1) mbar_arrive_expect(barF + cur * 8, SLICE);   // re-arm for t+2
                mbar_arrive_remote(mapa_u32(barE + cur * 8, peer));     // peer may overwrite B[cur]
                if (t > 1) {
                    mbar_wait(barE + nxt * 8, nxt ? pe1 : pe0);
                    if (nxt) pe1 ^= 1; else pe0 ^= 1;
                }
                fence_proxy_async_();
                bulk_s2s(mapa_u32(slb, peer), slb, SLICE, mapa_u32(barF + nxt * 8, peer));
                mbar_arrive_local(barF + nxt * 8);                      // local slice ready
            }
        }
        cur = nxt;
    }

    cluster_sync_();   // drain in-flight copies before smem teardown
}

// ---------------- launch ----------------
extern "C" void kernel_launch(void* const* d_in, const int* in_sizes, int n_in,
                              void* d_out, int out_size) {
    const int*   x     = (const int*)d_in[0];
    const int*   T     = (const int*)d_in[1];
    const float* pi    = (const float*)d_in[2];
    const float* trans = (const float*)d_in[3];
    const float* emis  = (const float*)d_in[4];
    float* out = (float*)d_out;

    cudaFuncSetAttribute(hmm_main, cudaFuncAttributeMaxDynamicSharedMemorySize, SMEM_BYTES);

    prep_pi<<<1, S>>>(pi);
    prep_A<<<S, 128>>>(trans);
    prep_E<<<S, 256>>>(emis);
    hmm_main<<<NCTAS, NT, SMEM_BYTES>>>(x, T, out);
}

// round 12
// speedup vs baseline: 1.4420x; 1.4420x over previous
#include <cuda_runtime.h>
#include <cuda_bf16.h>
#include <cstdint>

#define S       512
#define TMAXX   2048
#define OBS     1024
#define CL      4
#define BPC     4
#define NT      512
#define NCTAS   128

// B slice: 8 rows x 272B; rows 0-3 = v bf16[128], rows 4-7 zero except
// zp float4 at byte 1088 (start of row 4). Copy ships everything.
#define BROWB   272
#define SLICEB  2176
#define BUF_B   8704
#define ZPOFF   1088

// smem layout (bytes)
#define B_OFF   0                      // [2][4][SLICEB] = 17408
#define CP_OFF  17408                  // cp[8 pair][2 kh][16 n][4 b] f32 = 4096
#define ZR_OFF  (CP_OFF + 4096)        // zr[8 pair][4 b] f32 = 128
#define TS_OFF  (ZR_OFF + 128)         // Ts[4]
#define BAR_OFF (TS_OFF + 16)          // barF[2][4]=64B, barE[2]=16B
#define SMEM_BYTES (BAR_OFF + 96)

// ---------------- device tables ----------------
__device__ float g_expA[S * S];      // [n][p]
__device__ float g_expEt[OBS * S];   // [o][n]
__device__ float g_expPi[S];

// ---------------- helpers ----------------
__device__ __forceinline__ float warp_max(float v) {
    #pragma unroll
    for (int o = 16; o; o >>= 1) v = fmaxf(v, __shfl_xor_sync(0xffffffffu, v, o));
    return v;
}
__device__ __forceinline__ float warp_sum(float v) {
    #pragma unroll
    for (int o = 16; o; o >>= 1) v += __shfl_xor_sync(0xffffffffu, v, o);
    return v;
}
__device__ __forceinline__ uint32_t mapa_u32(uint32_t addr, int rank) {
    uint32_t r;
    asm("mapa.shared::cluster.u32 %0, %1, %2;" : "=r"(r) : "r"(addr), "r"(rank));
    return r;
}
__device__ __forceinline__ void mbar_init(uint32_t addr, uint32_t cnt) {
    asm volatile("mbarrier.init.shared.b64 [%0], %1;" :: "r"(addr), "r"(cnt) : "memory");
}
__device__ __forceinline__ void mbar_arrive_expect(uint32_t addr, uint32_t tx) {
    asm volatile("mbarrier.arrive.expect_tx.shared.b64 _, [%0], %1;" :: "r"(addr), "r"(tx) : "memory");
}
__device__ __forceinline__ void mbar_arrive_local(uint32_t addr) {
    asm volatile("mbarrier.arrive.shared.b64 _, [%0];" :: "r"(addr) : "memory");
}
__device__ __forceinline__ void mbar_arrive_remote(uint32_t remAddr) {
    asm volatile("mbarrier.arrive.shared::cluster.b64 _, [%0];" :: "r"(remAddr) : "memory");
}
__device__ __forceinline__ void mbar_wait(uint32_t addr, uint32_t parity) {
    uint32_t done;
    asm volatile(
        "{\n\t.reg .pred p;\n\t"
        "mbarrier.try_wait.parity.acquire.cta.shared::cta.b64 p, [%1], %2;\n\t"
        "selp.b32 %0, 1, 0, p;\n\t}"
        : "=r"(done) : "r"(addr), "r"(parity) : "memory");
    if (!done) {
        asm volatile(
            "{\n\t.reg .pred P1;\n\t"
            "WL_%=:\n\t"
            "mbarrier.try_wait.parity.acquire.cta.shared::cta.b64 P1, [%0], %1, 0x989680;\n\t"
            "@P1 bra.uni WD_%=;\n\t"
            "bra.uni WL_%=;\n\t"
            "WD_%=:\n\t}"
            :: "r"(addr), "r"(parity) : "memory");
    }
}
__device__ __forceinline__ void bulk_s2s(uint32_t dst_cluster, uint32_t src_cta,
                                         uint32_t bytes, uint32_t mbar_cluster) {
    asm volatile(
        "cp.async.bulk.shared::cluster.shared::cta.mbarrier::complete_tx::bytes [%0], [%1], %2, [%3];"
        :: "r"(dst_cluster), "r"(src_cta), "r"(bytes), "r"(mbar_cluster) : "memory");
}
__device__ __forceinline__ void fence_proxy_async_() {
    asm volatile("fence.proxy.async.shared::cta;" ::: "memory");
}
__device__ __forceinline__ void cluster_sync_() {
    asm volatile("barrier.cluster.arrive.aligned;\n" ::: "memory");
    asm volatile("barrier.cluster.wait.aligned;\n" ::: "memory");
}
__device__ __forceinline__ uint32_t pk_bf2(float lo, float hi) {
    __nv_bfloat162 h = __floats2bfloat162_rn(lo, hi);
    return *(uint32_t*)&h;
}
__device__ __forceinline__ uint32_t lds_u32(uint32_t addr) {
    uint32_t v;
    asm volatile("ld.shared.u32 %0, [%1];" : "=r"(v) : "r"(addr));
    return v;
}
__device__ __forceinline__ void mma16816(float& c0, float& c1, float& c2, float& c3,
                                         uint32_t a0, uint32_t a1, uint32_t a2, uint32_t a3,
                                         uint32_t b0, uint32_t b1) {
    asm volatile(
        "mma.sync.aligned.m16n8k16.row.col.f32.bf16.bf16.f32 "
        "{%0,%1,%2,%3}, {%4,%5,%6,%7}, {%8,%9}, {%0,%1,%2,%3};"
        : "+f"(c0), "+f"(c1), "+f"(c2), "+f"(c3)
        : "r"(a0), "r"(a1), "r"(a2), "r"(a3), "r"(b0), "r"(b1));
}

// ---------------- prep kernels (unchanged math) ----------------
__global__ void prep_pi(const float* __restrict__ pi) {
    __shared__ float red[16];
    int tid = threadIdx.x;
    float v = pi[tid];
    float m = warp_max(v);
    if ((tid & 31) == 0) red[tid >> 5] = m;
    __syncthreads();
    float bm = red[0];
    #pragma unroll
    for (int i = 1; i < 16; i++) bm = fmaxf(bm, red[i]);
    __syncthreads();
    float e = expf(v - bm);
    float s = warp_sum(e);
    if ((tid & 31) == 0) red[tid >> 5] = s;
    __syncthreads();
    float bs = 0.f;
    #pragma unroll
    for (int i = 0; i < 16; i++) bs += red[i];
    g_expPi[tid] = e / bs;
}

__global__ void prep_A(const float* __restrict__ trans) {
    __shared__ float red[4];
    int p = blockIdx.x, tid = threadIdx.x;
    int lane = tid & 31, w = tid >> 5;
    float v[4];
    #pragma unroll
    for (int k = 0; k < 4; k++) v[k] = trans[(tid + 128 * k) * S + p];
    float m = fmaxf(fmaxf(v[0], v[1]), fmaxf(v[2], v[3]));
    m = warp_max(m);
    if (lane == 0) red[w] = m;
    __syncthreads();
    float bm = fmaxf(fmaxf(red[0], red[1]), fmaxf(red[2], red[3]));
    __syncthreads();
    float e[4], s = 0.f;
    #pragma unroll
    for (int k = 0; k < 4; k++) { e[k] = expf(v[k] - bm); s += e[k]; }
    s = warp_sum(s);
    if (lane == 0) red[w] = s;
    __syncthreads();
    float bs = red[0] + red[1] + red[2] + red[3];
    float inv = 1.0f / bs;
    #pragma unroll
    for (int k = 0; k < 4; k++) g_expA[(tid + 128 * k) * S + p] = e[k] * inv;
}

__global__ void prep_E(const float* __restrict__ emis) {
    __shared__ float red[8];
    int n = blockIdx.x, tid = threadIdx.x;
    int lane = tid & 31, w = tid >> 5;
    float v[4];
    #pragma unroll
    for (int k = 0; k < 4; k++) v[k] = emis[n * OBS + tid + 256 * k];
    float m = fmaxf(fmaxf(v[0], v[1]), fmaxf(v[2], v[3]));
    m = warp_max(m);
    if (lane == 0) red[w] = m;
    __syncthreads();
    float bm = red[0];
    #pragma unroll
    for (int i = 1; i < 8; i++) bm = fmaxf(bm, red[i]);
    __syncthreads();
    float e[4], s = 0.f;
    #pragma unroll
    for (int k = 0; k < 4; k++) { e[k] = expf(v[k] - bm); s += e[k]; }
    s = warp_sum(s);
    if (lane == 0) red[w] = s;
    __syncthreads();
    float bs = 0.f;
    #pragma unroll
    for (int i = 0; i < 8; i++) bs += red[i];
    float inv = 1.0f / bs;
    #pragma unroll
    for (int k = 0; k < 4; k++) g_expEt[(tid + 256 * k) * S + n] = e[k] * inv;
}

// ---------------- main: HMMA scaled forward, decoupled warps ----------------
__global__ void __cluster_dims__(CL, 1, 1) __launch_bounds__(NT, 1)
hmm_main(const int* __restrict__ x, const int* __restrict__ T, float* __restrict__ out) {
    extern __shared__ char smc[];
    float* ZRf = (float*)(smc + ZR_OFF);
    int* Ts_sh = (int*)(smc + TS_OFF);

    const int tid  = threadIdx.x;
    const int wid  = tid >> 5, lane = tid & 31;
    const int rank = blockIdx.x & (CL - 1);
    const int b0   = (blockIdx.x >> 2) * BPC;
    const int nbase = rank * 128;

    const uint32_t smb  = (uint32_t)__cvta_generic_to_shared(smc);
    const uint32_t barF = smb + BAR_OFF;          // barF[buf][src] = barF + (buf*4+src)*8
    const uint32_t barE = smb + BAR_OFF + 64;     // barE[buf]

    // fragment / role coords
    const int g  = lane >> 2, tg = lane & 3;
    const int kh = wid & 1;                       // k half
    const int m  = wid >> 1;                      // pair id (0..7)
    const int mrow = m * 16;
    // epilogue coords (pair-local): batch and local n-column
    const int b_ep = kh * 2 + (lane >> 4);        // 0..3
    const int n_ep = mrow + (lane & 15);          // 0..127

    // ---- barriers ----
    if (tid == 0) {
        #pragma unroll
        for (int s = 0; s < 2; s++) {
            #pragma unroll
            for (int src = 0; src < CL; src++) {
                mbar_init(barF + (s * 4 + src) * 8, 1);
                if (src != rank) mbar_arrive_expect(barF + (s * 4 + src) * 8, SLICEB);
            }
            mbar_init(barE + s * 8, CL);
        }
    }
    if (tid < BPC) Ts_sh[tid] = T[b0 + tid];

    // ---- zero both B buffers ----
    for (int j = tid; j < 2 * BUF_B / 4; j += NT) ((uint32_t*)smc)[B_OFF / 4 + j] = 0u;
    __syncthreads();

    // ---- v0: all 4 slices locally, rows b<4 ----
    int xb0[BPC];
    #pragma unroll
    for (int b = 0; b < BPC; b++) xb0[b] = __ldg(&x[(b0 + b) * TMAXX]);
    for (int j = tid; j < 4 * BPC * 128; j += NT) {
        int s = j >> 9, b = (j >> 7) & 3, pl = j & 127;
        int p = s * 128 + pl;
        float v = __ldg(&g_expEt[xb0[b] * S + p]) * __ldg(&g_expPi[p]);
        *(uint16_t*)(smc + B_OFF + s * SLICEB + b * BROWB + pl * 2) =
            __bfloat16_as_ushort(__float2bfloat16(v));
    }
    // zp for buffer 0 (exact f32) at slice offset ZPOFF
    if (tid < 16) {
        int s = tid >> 2, b = tid & 3;
        float z = 0.f;
        for (int pl = 0; pl < 128; pl++) {
            int p = s * 128 + pl;
            z += __ldg(&g_expEt[xb0[b] * S + p]) * __ldg(&g_expPi[p]);
        }
        *(float*)(smc + B_OFF + s * SLICEB + ZPOFF + b * 4) = z;
    }

    // ---- A fragments resident in registers (64 regs) ----
    uint32_t Ar[16][4];
    {
        const float* r0p = &g_expA[(nbase + mrow + g) * S + kh * 256 + tg * 2];
        const float* r1p = r0p + 8 * S;
        #pragma unroll
        for (int c = 0; c < 16; c++) {
            const float* a0 = r0p + c * 16;
            const float* a1 = r1p + c * 16;
            Ar[c][0] = pk_bf2(__ldg(a0),     __ldg(a0 + 1));
            Ar[c][1] = pk_bf2(__ldg(a1),     __ldg(a1 + 1));
            Ar[c][2] = pk_bf2(__ldg(a0 + 8), __ldg(a0 + 9));
            Ar[c][3] = pk_bf2(__ldg(a1 + 8), __ldg(a1 + 9));
        }
    }
    __syncthreads();
    cluster_sync_();   // barriers + v0 visible before any comm

    int maxT = 0;
    #pragma unroll
    for (int b = 0; b < BPC; b++) maxT = max(maxT, Ts_sh[b]);

    double off = 0.0;                // warp 0 lanes 0..3 (batch = lane)
    int cur = 0;
    uint32_t pf0 = 0, pf1 = 0;       // full parities (per warp)
    uint32_t pe0 = 0, pe1 = 0;       // empty parities (warp0 lane0)

    for (int t = 1; ; ++t) {
        const int nxt = cur ^ 1;

        // ---- prefetch E for epilogue (this thread's (b_ep, n_ep)) ----
        int tt = t < TMAXX ? t : TMAXX - 1;
        int xbt = __ldg(&x[(b0 + b_ep) * TMAXX + tt]);
        float Ee = __ldg(&g_expEt[xbt * S + nbase + n_ep]);

        // ---- ALL warps wait all 4 slice barriers (incl local) ----
        if (t > 1) {
            uint32_t par = cur ? pf1 : pf0;
            #pragma unroll
            for (int s = 0; s < CL; s++) mbar_wait(barF + (cur * 4 + s) * 8, par);
            if (cur) pf1 ^= 1; else pf0 ^= 1;
        }

        // ---- per-warp rz for its two batches (lane 0; hidden under MMA) ----
        float rzA = 0.f, rzB = 0.f;
        if (lane == 0) {
            float zA = 0.f, zB = 0.f;
            #pragma unroll
            for (int s = 0; s < CL; s++) {
                float2 zp = *(float2*)(smc + B_OFF + cur * BUF_B + s * SLICEB + ZPOFF + kh * 8);
                zA += zp.x; zB += zp.y;
            }
            rzA = __fdividef(1.f, zA);
            rzB = __fdividef(1.f, zB);
        }

        // ---- warp0: exact out/off bookkeeping ----
        if (wid == 0 && lane < 16) {
            float z = *(float*)(smc + B_OFF + cur * BUF_B + (lane >> 2) * SLICEB + ZPOFF + (lane & 3) * 4);
            z += __shfl_xor_sync(0x0000ffffu, z, 4);
            z += __shfl_xor_sync(0x0000ffffu, z, 8);
            if (lane < 4) {
                float lz = logf(z);
                if (rank == 0 && Ts_sh[lane] == t) out[b0 + lane] = (float)(off + (double)lz);
                off += (double)lz;
            }
        }
        if (t == maxT) break;
        rzA = __shfl_sync(0xffffffffu, rzA, 0);
        rzB = __shfl_sync(0xffffffffu, rzB, 0);

        // ---- MMA: partial D over this warp's k half (R9-validated mapping) ----
        {
            const uint32_t vwb = smb + B_OFF + cur * BUF_B + kh * (2 * SLICEB)
                               + g * BROWB + tg * 4;
            float c0 = 0.f, c1 = 0.f, c2 = 0.f, c3 = 0.f;
            #pragma unroll
            for (int c = 0; c < 16; c++) {
                uint32_t boff = (uint32_t)((c >> 3) * SLICEB + (c & 7) * 32);
                uint32_t bb0 = lds_u32(vwb + boff);
                uint32_t bb1 = lds_u32(vwb + boff + 16);
                mma16816(c0, c1, c2, c3, Ar[c][0], Ar[c][1], Ar[c][2], Ar[c][3], bb0, bb1);
            }
            // CP[pair][kh][n16][b4], only batch cols 0-3 (tg<2)
            if (tg < 2) {
                uint32_t cpb = smb + CP_OFF + (uint32_t)(m * 512 + kh * 256 + tg * 8);
                *(float2*)(smc + (cpb - smb) + g * 16)       = make_float2(c0, c1);
                *(float2*)(smc + (cpb - smb) + (g + 8) * 16) = make_float2(c2, c3);
            }
        }
        // pair-scoped combine barrier
        asm volatile("bar.sync %0, 64;" :: "r"(2 + m) : "memory");

        // ---- epilogue (pair-local): combine k halves, scale, store, z partial ----
        {
            uint32_t cpi = (uint32_t)(CP_OFF + m * 512 + (lane & 15) * 16 + b_ep * 4);
            float c = *(float*)(smc + cpi) + *(float*)(smc + cpi + 256);
            float rz = (lane < 16) ? rzA : rzB;
            float w = c * Ee * rz;
            *(uint16_t*)(smc + B_OFF + nxt * BUF_B + rank * SLICEB + b_ep * BROWB + (lane & 15) * 2 + (mrow * 2)) =
                __bfloat16_as_ushort(__float2bfloat16(w));
            float zs = w;
            #pragma unroll
            for (int o = 1; o <= 8; o <<= 1) zs += __shfl_xor_sync(0xffffffffu, zs, o);
            if ((lane & 15) == 0) ZRf[m * 4 + b_ep] = zs;
        }

        // ---- main barrier: only warp0 blocks ----
        if (wid != 0) {
            asm volatile("bar.arrive 1, %0;" :: "r"(NT) : "memory");
        } else {
            asm volatile("bar.sync 1, %0;" :: "r"(NT) : "memory");
            const uint32_t slb = smb + B_OFF + nxt * BUF_B + rank * SLICEB;
            // zp totals over 8 pairs
            float zr = ZRf[lane];                      // pair=lane>>2, b=lane&3
            zr += __shfl_xor_sync(0xffffffffu, zr, 4);
            zr += __shfl_xor_sync(0xffffffffu, zr, 8);
            zr += __shfl_xor_sync(0xffffffffu, zr, 16);
            if (lane < 4) *(float*)(smc + (slb - smb) + ZPOFF + lane * 4) = zr;
            if (lane >= 4 && lane < 8) {
                int src = lane - 4;
                if (t > 1 && src != rank) mbar_arrive_expect(barF + (cur * 4 + src) * 8, SLICEB);
            }
            __syncwarp();
            if (lane == 0) mbar_arrive_local(barF + (nxt * 4 + rank) * 8);   // local slice ready
            if (lane >= 8 && lane < 8 + CL) {
                mbar_arrive_remote(mapa_u32(barE + cur * 8, lane - 8));      // buffer cur free
            }
            if (lane == 0) {
                if (t > 1) {
                    mbar_wait(barE + nxt * 8, nxt ? pe1 : pe0);
                    if (nxt) pe1 ^= 1; else pe0 ^= 1;
                }
                fence_proxy_async_();
                #pragma unroll
                for (int r = 0; r < CL; r++) {
                    if (r == rank) continue;
                    bulk_s2s(mapa_u32(slb, r), slb, SLICEB,
                             mapa_u32(barF + (nxt * 4 + rank) * 8, r));
                }
            }
        }
        cur = nxt;
    }

    cluster_sync_();   // drain in-flight copies before exit
}

// ---------------- launch ----------------
extern "C" void kernel_launch(void* const* d_in, const int* in_sizes, int n_in,
                              void* d_out, int out_size) {
    const int*   x     = (const int*)d_in[0];
    const int*   T     = (const int*)d_in[1];
    const float* pi    = (const float*)d_in[2];
    const float* trans = (const float*)d_in[3];
    const float* emis  = (const float*)d_in[4];
    float* out = (float*)d_out;

    cudaFuncSetAttribute(hmm_main, cudaFuncAttributeMaxDynamicSharedMemorySize, SMEM_BYTES);

    prep_pi<<<1, S>>>(pi);
    prep_A<<<S, 128>>>(trans);
    prep_E<<<S, 256>>>(emis);
    hmm_main<<<NCTAS, NT, SMEM_BYTES>>>(x, T, out);
}